// round 10
// baseline (speedup 1.0000x reference)
#include <cuda_runtime.h>
#include <cuda_fp16.h>
#include <cstdint>

#define WINDOW   128
#define EDIM     64
#define SEQQ     4096
#define NWIN     32
#define THREADS  256
// scale * log2(e): S computed in log2 domain, exp = ex2.approx
#define SCALE_L2E 0.180336880f

// padded smem row stride (halves): 144B -> ldmatrix row ptrs conflict-free
#define RS 72

// smem (half units): Q[128], K[256], V[256] row-major [row][e0..71]
#define O_Q  0
#define O_K  (O_Q + 128 * RS)
#define O_V  (O_K + 256 * RS)
#define SMEM_HALVES (O_V + 256 * RS)
#define SMEM_BYTES  ((SMEM_HALVES + 16) * 2)

__device__ __forceinline__ void mma16816(float* c, const uint32_t* a, const uint32_t* b) {
    asm volatile(
        "mma.sync.aligned.m16n8k16.row.col.f32.f16.f16.f32 "
        "{%0,%1,%2,%3}, {%4,%5,%6,%7}, {%8,%9}, {%0,%1,%2,%3};"
        : "+f"(c[0]), "+f"(c[1]), "+f"(c[2]), "+f"(c[3])
        : "r"(a[0]), "r"(a[1]), "r"(a[2]), "r"(a[3]), "r"(b[0]), "r"(b[1]));
}
__device__ __forceinline__ void ldm_x4(uint32_t* r, uint32_t addr) {
    asm volatile("ldmatrix.sync.aligned.m8n8.x4.shared.b16 {%0,%1,%2,%3}, [%4];"
        : "=r"(r[0]), "=r"(r[1]), "=r"(r[2]), "=r"(r[3]) : "r"(addr));
}
__device__ __forceinline__ void ldm_x4_t(uint32_t* r, uint32_t addr) {
    asm volatile("ldmatrix.sync.aligned.m8n8.x4.trans.shared.b16 {%0,%1,%2,%3}, [%4];"
        : "=r"(r[0]), "=r"(r[1]), "=r"(r[2]), "=r"(r[3]) : "r"(addr));
}
__device__ __forceinline__ void ldm_x2_t(uint32_t* r, uint32_t addr) {
    asm volatile("ldmatrix.sync.aligned.m8n8.x2.trans.shared.b16 {%0,%1}, [%2];"
        : "=r"(r[0]), "=r"(r[1]) : "r"(addr));
}
__device__ __forceinline__ uint32_t smem_u32(const void* p) {
    uint32_t a;
    asm("{ .reg .u64 t; cvta.to.shared.u64 t, %1; cvt.u32.u64 %0, t; }" : "=r"(a) : "l"(p));
    return a;
}
__device__ __forceinline__ float ex2f(float x) {
    float r;
    asm("ex2.approx.f32 %0, %1;" : "=f"(r) : "f"(x));
    return r;
}
__device__ __forceinline__ uint32_t pack_h2(float x, float y) {
    __half2 h = __floats2half2_rn(x, y);
    return *reinterpret_cast<uint32_t*>(&h);
}

// ---- S stage of a full 64-key chunk: QK^T, exp2, pack. s dies inside. ----
__device__ __forceinline__ void chunk_S4(
    int jb, uint32_t sbK, uint32_t koff,
    const uint32_t (&qa)[4][4], uint32_t (&pa)[4][4])
{
    float s[8][4];
    #pragma unroll
    for (int nt = 0; nt < 8; ++nt)
        #pragma unroll
        for (int i = 0; i < 4; ++i) s[nt][i] = 0.f;

    const uint32_t kcb = sbK + 2u * jb * RS + koff;
    #pragma unroll
    for (int ks = 0; ks < 4; ++ks) {
        #pragma unroll
        for (int ntp = 0; ntp < 4; ++ntp) {
            uint32_t b[4];
            ldm_x4(b, kcb + 2u * (16 * ntp * RS + 16 * ks));
            mma16816(s[2 * ntp],     qa[ks], b);
            mma16816(s[2 * ntp + 1], qa[ks], b + 2);
        }
    }
    #pragma unroll
    for (int nt = 0; nt < 8; ++nt) {
        s[nt][0] = ex2f(s[nt][0]);
        s[nt][1] = ex2f(s[nt][1]);
        s[nt][2] = ex2f(s[nt][2]);
        s[nt][3] = ex2f(s[nt][3]);
    }
    #pragma unroll
    for (int t = 0; t < 4; ++t) {
        pa[t][0] = pack_h2(s[2 * t][0],     s[2 * t][1]);
        pa[t][1] = pack_h2(s[2 * t][2],     s[2 * t][3]);
        pa[t][2] = pack_h2(s[2 * t + 1][0], s[2 * t + 1][1]);
        pa[t][3] = pack_h2(s[2 * t + 1][2], s[2 * t + 1][3]);
    }
}

// ---- PV stage of a full chunk (+ l ones-tile) ----
__device__ __forceinline__ void chunk_PV4(
    int jb, uint32_t sbV, uint32_t voff, uint32_t voff2,
    const uint32_t (&pa)[4][4], float (&o)[8][4], float (&oL)[4])
{
    const uint32_t vcb = sbV + 2u * jb * RS;
    #pragma unroll
    for (int t = 0; t < 4; ++t) {
        #pragma unroll
        for (int ep = 0; ep < 4; ++ep) {
            uint32_t b[4];
            ldm_x4_t(b, vcb + voff + 2u * (16 * t * RS + 16 * ep));
            mma16816(o[2 * ep],     pa[t], b);
            mma16816(o[2 * ep + 1], pa[t], b + 2);
        }
        uint32_t bl[2];
        ldm_x2_t(bl, vcb + voff2 + 2u * (16 * t * RS));
        mma16816(oL, pa[t], bl);
    }
}

// ---- full static chunk (masked diagonal variants, from R9) ----
template<int NT, bool DOMASK>
__device__ __forceinline__ void chunk_body(
    int jb, uint32_t sbK, uint32_t sbV,
    uint32_t koff, uint32_t voff, uint32_t voff2,
    const uint32_t (&qa)[4][4], float (&o)[8][4], float (&oL)[4],
    int lim0, int lim1)
{
    float s[2 * NT][4];
    #pragma unroll
    for (int nt = 0; nt < 2 * NT; ++nt)
        #pragma unroll
        for (int i = 0; i < 4; ++i) s[nt][i] = 0.f;

    const uint32_t kcb = sbK + 2u * jb * RS + koff;
    #pragma unroll
    for (int ks = 0; ks < 4; ++ks) {
        #pragma unroll
        for (int ntp = 0; ntp < NT; ++ntp) {
            uint32_t b[4];
            ldm_x4(b, kcb + 2u * (16 * ntp * RS + 16 * ks));
            mma16816(s[2 * ntp],     qa[ks], b);
            mma16816(s[2 * ntp + 1], qa[ks], b + 2);
        }
    }

    uint32_t pa[NT][4];
    #pragma unroll
    for (int nt = 0; nt < 2 * NT; ++nt) {
        const int col0 = jb + 8 * nt;
        float p0 = ex2f(s[nt][0]);
        float p1 = ex2f(s[nt][1]);
        float p2 = ex2f(s[nt][2]);
        float p3 = ex2f(s[nt][3]);
        if (DOMASK) {
            p0 = (col0     <= lim0) ? p0 : 0.f;
            p1 = (col0 + 1 <= lim0) ? p1 : 0.f;
            p2 = (col0     <= lim1) ? p2 : 0.f;
            p3 = (col0 + 1 <= lim1) ? p3 : 0.f;
        }
        s[nt][0] = p0; s[nt][1] = p1; s[nt][2] = p2; s[nt][3] = p3;
    }
    #pragma unroll
    for (int t = 0; t < NT; ++t) {
        pa[t][0] = pack_h2(s[2 * t][0],     s[2 * t][1]);
        pa[t][1] = pack_h2(s[2 * t][2],     s[2 * t][3]);
        pa[t][2] = pack_h2(s[2 * t + 1][0], s[2 * t + 1][1]);
        pa[t][3] = pack_h2(s[2 * t + 1][2], s[2 * t + 1][3]);
    }

    const uint32_t vcb = sbV + 2u * jb * RS;
    #pragma unroll
    for (int t = 0; t < NT; ++t) {
        #pragma unroll
        for (int ep = 0; ep < 4; ++ep) {
            uint32_t b[4];
            ldm_x4_t(b, vcb + voff + 2u * (16 * t * RS + 16 * ep));
            mma16816(o[2 * ep],     pa[t], b);
            mma16816(o[2 * ep + 1], pa[t], b + 2);
        }
        uint32_t bl[2];
        ldm_x2_t(bl, vcb + voff2 + 2u * (16 * t * RS));
        mma16816(oL, pa[t], bl);
    }
}

// stage one quarter of part-2 (rows 128..255) of K or V: 4 float4/thread
#define STAGE_P2(DST, GP, IT0, IT1)                                          \
    do {                                                                     \
        _Pragma("unroll")                                                    \
        for (int it = (IT0); it < (IT1); ++it) {                             \
            int idx = it * THREADS + tid + 2048;                             \
            int row = idx >> 4, c4 = idx & 15;                               \
            float4 f = (GP)[idx];                                            \
            __half2 a = __floats2half2_rn(f.x, f.y);                         \
            __half2 b = __floats2half2_rn(f.z, f.w);                         \
            *(uint2*)&smem[(DST) + row * RS + 4 * c4] =                      \
                make_uint2(*(uint32_t*)&a, *(uint32_t*)&b);                  \
        }                                                                    \
    } while (0)

__global__ __launch_bounds__(THREADS, 2)
void lattn_hmma(const float* __restrict__ q, const float* __restrict__ k,
                const float* __restrict__ v, float* __restrict__ out)
{
    extern __shared__ __half smem[];
    const uint32_t sb  = smem_u32(smem);
    const uint32_t sbQ = sb;
    const uint32_t sbK = sb + O_K * 2;
    const uint32_t sbV = sb + O_V * 2;

    const int tid = threadIdx.x;
    const int w   = tid >> 5;
    const int ln  = tid & 31;
    const int g   = ln >> 2;
    const int tig = ln & 3;
    // balanced SMSP map: warps {s, s+4} host wl {s, 7-s}
    const int wl  = (w < 4) ? w : 11 - w;
    const int win = blockIdx.x;
    const int bh  = blockIdx.y;
    const bool have_back = (win > 0);

    const long long qrow0 = (long long)bh * SEQQ + (long long)win * WINDOW;
    const long long krow0 = qrow0 - WINDOW;

    const float4* qg4 = (const float4*)(q + qrow0 * EDIM);
    const float4* kg4 = (const float4*)(k + krow0 * EDIM);
    const float4* vg4 = (const float4*)(v + krow0 * EDIM);

    // ---- phase 1: Q (scaled), K/V rows 0..127, ones column (all rows) ----
    {
        #pragma unroll
        for (int it = 0; it < 8; ++it) {
            int idx = it * THREADS + tid;       // 0..2047
            int row = idx >> 4, c4 = idx & 15;
            float4 f = qg4[idx];
            __half2 a = __floats2half2_rn(f.x * SCALE_L2E, f.y * SCALE_L2E);
            __half2 b = __floats2half2_rn(f.z * SCALE_L2E, f.w * SCALE_L2E);
            *(uint2*)&smem[O_Q + row * RS + 4 * c4] =
                make_uint2(*(uint32_t*)&a, *(uint32_t*)&b);
        }
        if (have_back) {
            #pragma unroll
            for (int it = 0; it < 8; ++it) {
                int idx = it * THREADS + tid;   // rows 0..127
                int row = idx >> 4, c4 = idx & 15;
                float4 fk = kg4[idx];
                float4 fv = vg4[idx];
                __half2 ka = __floats2half2_rn(fk.x, fk.y);
                __half2 kb = __floats2half2_rn(fk.z, fk.w);
                __half2 va = __floats2half2_rn(fv.x, fv.y);
                __half2 vb = __floats2half2_rn(fv.z, fv.w);
                *(uint2*)&smem[O_K + row * RS + 4 * c4] =
                    make_uint2(*(uint32_t*)&ka, *(uint32_t*)&kb);
                *(uint2*)&smem[O_V + row * RS + 4 * c4] =
                    make_uint2(*(uint32_t*)&va, *(uint32_t*)&vb);
            }
        }
        // V ones-column at e=64 (l = P @ ones), zeros at 65..71, all 256 rows
        const __half2 one0 = __floats2half2_rn(1.f, 0.f);
        const __half2 zz   = __floats2half2_rn(0.f, 0.f);
        #pragma unroll
        for (int it = 0; it < 4; ++it) {
            int idx = it * THREADS + tid;
            int row = idx >> 2, cc = idx & 3;
            *(__half2*)&smem[O_V + row * RS + 64 + 2 * cc] = (cc == 0) ? one0 : zz;
        }
    }
    __syncthreads();

    const int row0 = 16 * wl + g;
    const int row1 = row0 + 8;

    // per-lane ldmatrix base offsets (bytes)
    const uint32_t koff  = 2u * (((ln & 7) + ((ln & 16) >> 1)) * RS + (ln & 8));
    const uint32_t voff  = 2u * (((ln & 7) + (ln & 8)) * RS + ((ln & 16) >> 1));
    const uint32_t voff2 = 2u * (((ln & 7) + (ln & 8)) * RS + 64);

    // ---- resident Q A-fragments ----
    uint32_t qa[4][4];
    {
        const uint32_t qbase = sbQ + 2u * (16 * wl) * RS + voff;
        #pragma unroll
        for (int ks = 0; ks < 4; ++ks)
            ldm_x4(qa[ks], qbase + 2u * 16 * ks);
    }

    float o[8][4];
    #pragma unroll
    for (int nt = 0; nt < 8; ++nt)
        #pragma unroll
        for (int i = 0; i < 4; ++i) o[nt][i] = 0.f;
    float oL[4] = {0.f, 0.f, 0.f, 0.f};

    // ---- chunks 0,1 (unmasked) interleaved with part-2 staging ----
    if (have_back) {
        uint32_t pa[4][4];
        chunk_S4(0, sbK, koff, qa, pa);
        STAGE_P2(O_K, kg4, 0, 4);            // K rows 128..191
        chunk_PV4(0, sbV, voff, voff2, pa, o, oL);
        STAGE_P2(O_K, kg4, 4, 8);            // K rows 192..255
        chunk_S4(64, sbK, koff, qa, pa);
        STAGE_P2(O_V, vg4, 0, 4);            // V rows 128..191
        chunk_PV4(64, sbV, voff, voff2, pa, o, oL);
        STAGE_P2(O_V, vg4, 4, 8);            // V rows 192..255
    } else {
        STAGE_P2(O_K, kg4, 0, 8);
        STAGE_P2(O_V, vg4, 0, 8);
    }
    __syncthreads();

    // lims pre-shifted by -2*tig so chunk body compares against jb+8nt(+1)
    const int lim0 = row0 + WINDOW - 2 * tig;
    const int lim1 = row1 + WINDOW - 2 * tig;

    // chunk 2 (keys 128..191): rows 0..31 only see keys <=159 -> 2 tiles
    if (wl < 2)
        chunk_body<2, true>(128, sbK, sbV, koff, voff, voff2, qa, o, oL, lim0, lim1);
    else
        chunk_body<4, true>(128, sbK, sbV, koff, voff, voff2, qa, o, oL, lim0, lim1);
    // chunk 3 (keys 192..255): rows <64 see none; rows 64..95 see <=223 -> 2 tiles
    if (wl >= 4) {
        if (wl < 6)
            chunk_body<2, true>(192, sbK, sbV, koff, voff, voff2, qa, o, oL, lim0, lim1);
        else
            chunk_body<4, true>(192, sbK, sbV, koff, voff, voff2, qa, o, oL, lim0, lim1);
    }

    // ---- l from ones column (tig==0 lanes), normalize, store ----
    const float l0 = __shfl_sync(0xFFFFFFFFu, oL[0], ln & 28);
    const float l1 = __shfl_sync(0xFFFFFFFFu, oL[2], ln & 28);
    const float r0 = 1.f / l0;
    const float r1 = 1.f / l1;

    float* ob = out + qrow0 * EDIM;
    #pragma unroll
    for (int nt = 0; nt < 8; ++nt) {
        int e0 = 8 * nt + 2 * tig;
        float2 v0 = make_float2(o[nt][0] * r0, o[nt][1] * r0);
        float2 v1 = make_float2(o[nt][2] * r1, o[nt][3] * r1);
        *(float2*)&ob[(long long)row0 * EDIM + e0] = v0;
        *(float2*)&ob[(long long)row1 * EDIM + e0] = v1;
    }
}

extern "C" void kernel_launch(void* const* d_in, const int* in_sizes, int n_in,
                              void* d_out, int out_size)
{
    const float* q = (const float*)d_in[0];
    const float* k = (const float*)d_in[1];
    const float* v = (const float*)d_in[2];
    float* out = (float*)d_out;

    const int bh_count = in_sizes[0] / (SEQQ * EDIM);   // b*h = 32

    cudaFuncSetAttribute(lattn_hmma, cudaFuncAttributeMaxDynamicSharedMemorySize, SMEM_BYTES);

    dim3 grid(NWIN, bh_count);
    lattn_hmma<<<grid, THREADS, SMEM_BYTES>>>(q, k, v, out);
}

// round 11
// speedup vs baseline: 1.1019x; 1.1019x over previous
#include <cuda_runtime.h>
#include <cuda_fp16.h>
#include <cstdint>

#define WINDOW   128
#define EDIM     64
#define SEQQ     4096
#define NWIN     32
#define THREADS  256
// scale * log2(e): S computed in log2 domain, exp = ex2.approx
#define SCALE_L2E 0.180336880f

// padded smem row stride (halves): 144B -> ldmatrix row ptrs conflict-free
#define RS 72

// smem (half units): Q[128], K[256], V[256] row-major [row][e0..71]
#define O_Q  0
#define O_K  (O_Q + 128 * RS)
#define O_V  (O_K + 256 * RS)
#define SMEM_HALVES (O_V + 256 * RS)
#define SMEM_BYTES  ((SMEM_HALVES + 16) * 2)

// fp32-accumulating HMMA (for O and l)
__device__ __forceinline__ void mma16816(float* c, const uint32_t* a, const uint32_t* b) {
    asm volatile(
        "mma.sync.aligned.m16n8k16.row.col.f32.f16.f16.f32 "
        "{%0,%1,%2,%3}, {%4,%5,%6,%7}, {%8,%9}, {%0,%1,%2,%3};"
        : "+f"(c[0]), "+f"(c[1]), "+f"(c[2]), "+f"(c[3])
        : "r"(a[0]), "r"(a[1]), "r"(a[2]), "r"(a[3]), "r"(b[0]), "r"(b[1]));
}
// fp16-accumulating HMMA (for S): C/D = 2 packed half2 regs
__device__ __forceinline__ void mma16816h(uint32_t* c, const uint32_t* a, const uint32_t* b) {
    asm volatile(
        "mma.sync.aligned.m16n8k16.row.col.f16.f16.f16.f16 "
        "{%0,%1}, {%2,%3,%4,%5}, {%6,%7}, {%0,%1};"
        : "+r"(c[0]), "+r"(c[1])
        : "r"(a[0]), "r"(a[1]), "r"(a[2]), "r"(a[3]), "r"(b[0]), "r"(b[1]));
}
__device__ __forceinline__ void ldm_x4(uint32_t* r, uint32_t addr) {
    asm volatile("ldmatrix.sync.aligned.m8n8.x4.shared.b16 {%0,%1,%2,%3}, [%4];"
        : "=r"(r[0]), "=r"(r[1]), "=r"(r[2]), "=r"(r[3]) : "r"(addr));
}
__device__ __forceinline__ void ldm_x4_t(uint32_t* r, uint32_t addr) {
    asm volatile("ldmatrix.sync.aligned.m8n8.x4.trans.shared.b16 {%0,%1,%2,%3}, [%4];"
        : "=r"(r[0]), "=r"(r[1]), "=r"(r[2]), "=r"(r[3]) : "r"(addr));
}
__device__ __forceinline__ void ldm_x2_t(uint32_t* r, uint32_t addr) {
    asm volatile("ldmatrix.sync.aligned.m8n8.x2.trans.shared.b16 {%0,%1}, [%2];"
        : "=r"(r[0]), "=r"(r[1]) : "r"(addr));
}
__device__ __forceinline__ uint32_t smem_u32(const void* p) {
    uint32_t a;
    asm("{ .reg .u64 t; cvta.to.shared.u64 t, %1; cvt.u32.u64 %0, t; }" : "=r"(a) : "l"(p));
    return a;
}
__device__ __forceinline__ uint32_t ex2_h2(uint32_t x) {
    uint32_t r;
    asm("ex2.approx.f16x2 %0, %1;" : "=r"(r) : "r"(x));
    return r;
}
__device__ __forceinline__ uint32_t mul_h2(uint32_t a, uint32_t b) {
    uint32_t r;
    asm("mul.rn.f16x2 %0, %1, %2;" : "=r"(r) : "r"(a), "r"(b));
    return r;
}

// One key-chunk: fp16-acc S MMAs -> f16x2 exp (+0/1 mask mul) -> PV (fp32 acc).
// The fp16 S C-fragment IS the PV A-fragment: zero repack.
template<int NT, bool DOMASK>
__device__ __forceinline__ void chunk_body(
    int jb, uint32_t sbK, uint32_t sbV,
    uint32_t koff, uint32_t voff, uint32_t voff2,
    const uint32_t (&qa)[4][4], float (&o)[8][4], float (&oL)[4],
    int lim0, int lim1)
{
    // s2[nt][0] = rows g,   cols (jb+8nt+2tig, +1)  packed half2
    // s2[nt][1] = rows g+8, same cols
    uint32_t s2[2 * NT][2];
    #pragma unroll
    for (int nt = 0; nt < 2 * NT; ++nt) { s2[nt][0] = 0u; s2[nt][1] = 0u; }

    const uint32_t kcb = sbK + 2u * jb * RS + koff;
    #pragma unroll
    for (int ks = 0; ks < 4; ++ks) {
        #pragma unroll
        for (int ntp = 0; ntp < NT; ++ntp) {
            uint32_t b[4];
            ldm_x4(b, kcb + 2u * (16 * ntp * RS + 16 * ks));
            mma16816h(s2[2 * ntp],     qa[ks], b);
            mma16816h(s2[2 * ntp + 1], qa[ks], b + 2);
        }
    }

    // exp2 in fp16, then zero masked lanes via 0/1 half2 multiply
    #pragma unroll
    for (int nt = 0; nt < 2 * NT; ++nt) {
        uint32_t p0 = ex2_h2(s2[nt][0]);
        uint32_t p1 = ex2_h2(s2[nt][1]);
        if (DOMASK) {
            const int col0 = jb + 8 * nt;          // caller folded 2*tig into lims
            uint32_t m0 = (col0 <= lim0 ? 0x3C00u : 0u) | (col0 + 1 <= lim0 ? 0x3C000000u : 0u);
            uint32_t m1 = (col0 <= lim1 ? 0x3C00u : 0u) | (col0 + 1 <= lim1 ? 0x3C000000u : 0u);
            p0 = mul_h2(p0, m0);
            p1 = mul_h2(p1, m1);
        }
        s2[nt][0] = p0;
        s2[nt][1] = p1;
    }

    const uint32_t vcb = sbV + 2u * jb * RS;
    #pragma unroll
    for (int t = 0; t < NT; ++t) {
        // A-fragment for keys 16t..16t+15 (FA2 layout identity)
        uint32_t pa[4] = { s2[2 * t][0], s2[2 * t][1], s2[2 * t + 1][0], s2[2 * t + 1][1] };
        #pragma unroll
        for (int ep = 0; ep < 4; ++ep) {
            uint32_t b[4];
            ldm_x4_t(b, vcb + voff + 2u * (16 * t * RS + 16 * ep));
            mma16816(o[2 * ep],     pa, b);
            mma16816(o[2 * ep + 1], pa, b + 2);
        }
        uint32_t bl[2];
        ldm_x2_t(bl, vcb + voff2 + 2u * (16 * t * RS));
        mma16816(oL, pa, bl);
    }
}

__global__ __launch_bounds__(THREADS, 2)
void lattn_hmma(const float* __restrict__ q, const float* __restrict__ k,
                const float* __restrict__ v, float* __restrict__ out)
{
    extern __shared__ __half smem[];
    const uint32_t sb  = smem_u32(smem);
    const uint32_t sbQ = sb;
    const uint32_t sbK = sb + O_K * 2;
    const uint32_t sbV = sb + O_V * 2;

    const int tid = threadIdx.x;
    const int w   = tid >> 5;
    const int ln  = tid & 31;
    const int g   = ln >> 2;
    const int tig = ln & 3;
    // balanced SMSP map: warps {s, s+4} host wl {s, 7-s}
    const int wl  = (w < 4) ? w : 11 - w;
    const int win = blockIdx.x;
    const int bh  = blockIdx.y;
    const bool have_back = (win > 0);

    const long long qrow0 = (long long)bh * SEQQ + (long long)win * WINDOW;
    const long long krow0 = qrow0 - WINDOW;

    // ---- stage Q (scaled by scale*log2e), K, V row-major (R9-identical) ----
    {
        const float2* qg = (const float2*)(q + qrow0 * EDIM);
        #pragma unroll
        for (int it = 0; it < 16; ++it) {
            int idx = it * THREADS + tid;
            int row = idx >> 5, c2 = idx & 31;
            float2 f = qg[idx];
            *(__half2*)&smem[O_Q + row * RS + 2 * c2] =
                __floats2half2_rn(f.x * SCALE_L2E, f.y * SCALE_L2E);
        }
        const float2* kg = (const float2*)(k + krow0 * EDIM);
        const float2* vg = (const float2*)(v + krow0 * EDIM);
        #pragma unroll
        for (int it = 0; it < 32; ++it) {
            int idx = it * THREADS + tid;
            int row = idx >> 5, c2 = idx & 31;
            if (have_back || row >= WINDOW) {
                float2 fk = kg[idx];
                float2 fv = vg[idx];
                *(__half2*)&smem[O_K + row * RS + 2 * c2] = __floats2half2_rn(fk.x, fk.y);
                *(__half2*)&smem[O_V + row * RS + 2 * c2] = __floats2half2_rn(fv.x, fv.y);
            }
        }
        // V ones-column at e=64 (l = P @ ones), zeros at 65..71
        const __half2 one0 = __floats2half2_rn(1.f, 0.f);
        const __half2 zz   = __floats2half2_rn(0.f, 0.f);
        #pragma unroll
        for (int it = 0; it < 4; ++it) {
            int idx = it * THREADS + tid;
            int row = idx >> 2, cc = idx & 3;
            *(__half2*)&smem[O_V + row * RS + 64 + 2 * cc] = (cc == 0) ? one0 : zz;
        }
    }
    __syncthreads();

    const int row0 = 16 * wl + g;
    const int row1 = row0 + 8;

    // per-lane ldmatrix base offsets (bytes)
    const uint32_t koff  = 2u * (((ln & 7) + ((ln & 16) >> 1)) * RS + (ln & 8));
    const uint32_t voff  = 2u * (((ln & 7) + (ln & 8)) * RS + ((ln & 16) >> 1));
    const uint32_t voff2 = 2u * (((ln & 7) + (ln & 8)) * RS + 64);

    // ---- resident Q A-fragments ----
    uint32_t qa[4][4];
    {
        const uint32_t qbase = sbQ + 2u * (16 * wl) * RS + voff;
        #pragma unroll
        for (int ks = 0; ks < 4; ++ks)
            ldm_x4(qa[ks], qbase + 2u * 16 * ks);
    }

    float o[8][4];
    #pragma unroll
    for (int nt = 0; nt < 8; ++nt)
        #pragma unroll
        for (int i = 0; i < 4; ++i) o[nt][i] = 0.f;
    float oL[4] = {0.f, 0.f, 0.f, 0.f};

    // lims pre-shifted by -2*tig so chunk body compares against jb+8nt(+1)
    const int lim0 = row0 + WINDOW - 2 * tig;
    const int lim1 = row1 + WINDOW - 2 * tig;

    // chunks 0,1: unmasked, all 4 tiles (skip for window 0)
    if (have_back) {
        chunk_body<4, false>(0,  sbK, sbV, koff, voff, voff2, qa, o, oL, lim0, lim1);
        chunk_body<4, false>(64, sbK, sbV, koff, voff, voff2, qa, o, oL, lim0, lim1);
    }
    // chunk 2 (keys 128..191): rows 0..31 only ever see keys <=159 -> 2 tiles
    if (wl < 2)
        chunk_body<2, true>(128, sbK, sbV, koff, voff, voff2, qa, o, oL, lim0, lim1);
    else
        chunk_body<4, true>(128, sbK, sbV, koff, voff, voff2, qa, o, oL, lim0, lim1);
    // chunk 3 (keys 192..255): rows <64 see none; rows 64..95 see <=223 -> 2 tiles
    if (wl >= 4) {
        if (wl < 6)
            chunk_body<2, true>(192, sbK, sbV, koff, voff, voff2, qa, o, oL, lim0, lim1);
        else
            chunk_body<4, true>(192, sbK, sbV, koff, voff, voff2, qa, o, oL, lim0, lim1);
    }

    // ---- l from ones column (tig==0 lanes), normalize, store ----
    const float l0 = __shfl_sync(0xFFFFFFFFu, oL[0], ln & 28);
    const float l1 = __shfl_sync(0xFFFFFFFFu, oL[2], ln & 28);
    const float r0 = 1.f / l0;
    const float r1 = 1.f / l1;

    float* ob = out + qrow0 * EDIM;
    #pragma unroll
    for (int nt = 0; nt < 8; ++nt) {
        int e0 = 8 * nt + 2 * tig;
        float2 v0 = make_float2(o[nt][0] * r0, o[nt][1] * r0);
        float2 v1 = make_float2(o[nt][2] * r1, o[nt][3] * r1);
        *(float2*)&ob[(long long)row0 * EDIM + e0] = v0;
        *(float2*)&ob[(long long)row1 * EDIM + e0] = v1;
    }
}

extern "C" void kernel_launch(void* const* d_in, const int* in_sizes, int n_in,
                              void* d_out, int out_size)
{
    const float* q = (const float*)d_in[0];
    const float* k = (const float*)d_in[1];
    const float* v = (const float*)d_in[2];
    float* out = (float*)d_out;

    const int bh_count = in_sizes[0] / (SEQQ * EDIM);   // b*h = 32

    cudaFuncSetAttribute(lattn_hmma, cudaFuncAttributeMaxDynamicSharedMemorySize, SMEM_BYTES);

    dim3 grid(NWIN, bh_count);
    lattn_hmma<<<grid, THREADS, SMEM_BYTES>>>(q, k, v, out);
}